// round 8
// baseline (speedup 1.0000x reference)
#include <cuda_runtime.h>
#include <cuda_fp16.h>
#include <math.h>
#include <stdint.h>

// ---------------------------------------------------------------- constants
#define BSZ   16384
#define INSZ  512
#define OUTSZ 512
#define ORD   10
#define KTOT  5632              // 512 silu + 10*512 scrambled chebyshev
#define BM    128
#define BN    128
#define BK    64
#define NKT   (KTOT / BK)       // 88
#define STAGES 3
#define STAGE_BYTES 32768       // A 16KB + B 16KB
#define SMEM_BYTES  (STAGES * STAGE_BYTES)   // 98304

// ---------------------------------------------------------------- scratch
__device__ __align__(16) __half g_a[(size_t)BSZ * KTOT];   // 176 MB
__device__ __align__(16) __half g_b[(size_t)OUTSZ * KTOT]; // 5.6 MB

// --------------------------------------------------------- merged builder
// blocks [0, BSZ):        Act rows (scrambled chebyshev + silu)
// blocks [BSZ, BSZ+5632): Wc, 512 elements per block
__global__ void build_all_kernel(const float* __restrict__ x,
                                 const float* __restrict__ base_w,
                                 const float* __restrict__ cheby_w) {
    int blk = blockIdx.x;
    int i   = threadIdx.x;                     // 0..511
    if (blk < BSZ) {
        int bb = blk;
        float xv = x[bb * INSZ + i];
        float s = xv / (1.0f + expf(-xv));
        g_a[(size_t)bb * KTOT + i] = __float2half_rn(s);

        float tm2 = 1.0f, tm1 = xv;
        #pragma unroll
        for (int o = 0; o < ORD; o++) {
            float t;
            if (o == 0)      t = 1.0f;
            else if (o == 1) t = xv;
            else { t = 2.0f * xv * tm1 - tm2; tm2 = tm1; tm1 = t; }
            int m  = o * BSZ + bb;
            int b  = m / 10;
            int op = m - b * 10;
            g_a[(size_t)b * KTOT + INSZ + op * INSZ + i] = __float2half_rn(t);
        }
    } else {
        int idx = (blk - BSZ) * 512 + i;
        int out = idx / KTOT;
        int k   = idx - out * KTOT;
        float v = (k < INSZ) ? base_w[out * INSZ + k]
                             : 0.1f * cheby_w[out * (INSZ * ORD) + (k - INSZ)];
        g_b[idx] = __float2half_rn(v);
    }
}

// --------------------------------------------------------- PTX primitives
__device__ __forceinline__ uint32_t smem_u32(const void* p) {
    uint32_t a;
    asm("{ .reg .u64 t; cvta.to.shared.u64 t, %1; cvt.u32.u64 %0, t; }" : "=r"(a) : "l"(p));
    return a;
}
__device__ __forceinline__ void cp16(uint32_t dst, const void* src) {
    asm volatile("cp.async.cg.shared.global [%0], [%1], 16;" :: "r"(dst), "l"(src));
}
#define LDSM_X4(d0, d1, d2, d3, addr)                                          \
    asm volatile("ldmatrix.sync.aligned.m8n8.x4.shared.b16 {%0,%1,%2,%3}, [%4];" \
                 : "=r"(d0), "=r"(d1), "=r"(d2), "=r"(d3) : "r"(addr))
#define HMMA(acc, a, b0, b1)                                                   \
    asm volatile("mma.sync.aligned.m16n8k16.row.col.f32.f16.f16.f32 "          \
                 "{%0,%1,%2,%3}, {%4,%5,%6,%7}, {%8,%9}, {%0,%1,%2,%3};"       \
                 : "+f"(acc[0]), "+f"(acc[1]), "+f"(acc[2]), "+f"(acc[3])      \
                 : "r"(a[0]), "r"(a[1]), "r"(a[2]), "r"(a[3]), "r"(b0), "r"(b1))

// ------------------------------------------------------------- HMMA GEMM
// C[16384,512] = A[16384,5632] @ B[512,5632]^T, fp16 in, fp32 accum.
// CTA 128x128, BK=64, 3-stage cp.async pipeline, 4 warps (2x2), 128 threads,
// warp tile 64x64 (halves smem read amplification vs 64x32).
// Chunk-level software pipeline: transition before the trailing ks=3 MMAs.
__global__ void __launch_bounds__(128, 2) gemm_hmma_kernel(float* __restrict__ out) {
    extern __shared__ char smem[];
    uint32_t su = smem_u32(smem);
    int tid = threadIdx.x, lane = tid & 31, wid = tid >> 5;
    int mOff = (wid & 1) * 64;
    int nOff = (wid >> 1) * 64;
    int rowBase = blockIdx.y * BM;
    int colBase = blockIdx.x * BN;

    const __half* Ag = g_a + (size_t)rowBase * KTOT;
    const __half* Bg = g_b + (size_t)colBase * KTOT;

    // loader mapping: 128 threads, row = tid, all 8 16B-chunks of that row
    const __half* agb = Ag + (size_t)tid * KTOT;
    const __half* bgb = Bg + (size_t)tid * KTOT;

    float acc[4][8][4];
    #pragma unroll
    for (int mi = 0; mi < 4; mi++)
        #pragma unroll
        for (int ni = 0; ni < 8; ni++)
            #pragma unroll
            for (int q = 0; q < 4; q++) acc[mi][ni][q] = 0.0f;

    int f_r = lane & 15, f_k = lane >> 4;   // ldmatrix x4 lane mapping

    uint32_t af[2][4][4];   // [buf][mi][4]
    uint32_t bf[2][4][4];   // [buf][npair][4]; regs {0,2}->ni even, {1,3}->ni odd

    // issue global loads for chunks 0, 1
    #pragma unroll
    for (int p = 0; p < 2; p++) {
        uint32_t sa = su + p * STAGE_BYTES, sb = sa + 16384;
        #pragma unroll
        for (int c = 0; c < 8; c++) {
            uint32_t off = (uint32_t)(tid * 128 + ((c ^ (tid & 7)) * 16));
            cp16(sa + off, agb + p * BK + c * 8);
            cp16(sb + off, bgb + p * BK + c * 8);
        }
        asm volatile("cp.async.commit_group;" ::: "memory");
    }

    auto load_frags = [&](uint32_t sa, uint32_t sb, int ks, int bu) {
        int c = ks * 2 + f_k;
        #pragma unroll
        for (int mi = 0; mi < 4; mi++) {
            int r = mOff + mi * 16 + f_r;
            uint32_t ad = sa + (uint32_t)(r * 128 + ((c ^ (r & 7)) * 16));
            LDSM_X4(af[bu][mi][0], af[bu][mi][1], af[bu][mi][2], af[bu][mi][3], ad);
        }
        #pragma unroll
        for (int p = 0; p < 4; p++) {
            int r = nOff + p * 16 + f_r;
            uint32_t bd = sb + (uint32_t)(r * 128 + ((c ^ (r & 7)) * 16));
            LDSM_X4(bf[bu][p][0], bf[bu][p][1], bf[bu][p][2], bf[bu][p][3], bd);
        }
    };
    auto mma_step = [&](int bu) {
        #pragma unroll
        for (int mi = 0; mi < 4; mi++)
            #pragma unroll
            for (int p = 0; p < 4; p++) {
                HMMA(acc[mi][2 * p],     af[bu][mi], bf[bu][p][0], bf[bu][p][2]);
                HMMA(acc[mi][2 * p + 1], af[bu][mi], bf[bu][p][1], bf[bu][p][3]);
            }
    };

    // prologue: drain chunk 0, publish, load its ks0 fragments
    asm volatile("cp.async.wait_group 1;" ::: "memory");
    __syncthreads();
    load_frags(su, su + 16384, 0, 0);

    for (int kt = 0; kt < NKT; kt++) {
        uint32_t sa = su + (kt % STAGES) * STAGE_BYTES, sb = sa + 16384;

        #pragma unroll
        for (int ks = 0; ks < 3; ks++) {
            load_frags(sa, sb, ks + 1, (ks & 1) ^ 1);   // prefetch ks+1 frags
            mma_step(ks & 1);                            // MMA ks
        }

        // ---- transition (hidden under the trailing ks=3 MMAs) ----
        if (kt + 1 < NKT) {
            asm volatile("cp.async.wait_group 0;" ::: "memory");   // drain kt+1
            __syncthreads();
            uint32_t na = su + ((kt + 1) % STAGES) * STAGE_BYTES, nb = na + 16384;
            load_frags(na, nb, 0, 0);                    // next chunk ks0 -> buf 0
            if (kt + 2 < NKT) {                          // issue chunk kt+2
                uint32_t pa = su + ((kt + 2) % STAGES) * STAGE_BYTES, pb = pa + 16384;
                #pragma unroll
                for (int c = 0; c < 8; c++) {
                    uint32_t off = (uint32_t)(tid * 128 + ((c ^ (tid & 7)) * 16));
                    cp16(pa + off, agb + (size_t)(kt + 2) * BK + c * 8);
                    cp16(pb + off, bgb + (size_t)(kt + 2) * BK + c * 8);
                }
                asm volatile("cp.async.commit_group;" ::: "memory");
            }
        }

        mma_step(1);                                     // MMA ks=3 (buf 1)
    }

    // epilogue: C fragment layout -> float2 global stores
    int gid = lane >> 2, tig = lane & 3;
    #pragma unroll
    for (int mi = 0; mi < 4; mi++) {
        int r0 = rowBase + mOff + mi * 16 + gid;
        #pragma unroll
        for (int ni = 0; ni < 8; ni++) {
            int cc = colBase + nOff + ni * 8 + tig * 2;
            float2 v0 = make_float2(acc[mi][ni][0], acc[mi][ni][1]);
            float2 v1 = make_float2(acc[mi][ni][2], acc[mi][ni][3]);
            *(float2*)&out[(size_t)r0 * OUTSZ + cc]       = v0;
            *(float2*)&out[(size_t)(r0 + 8) * OUTSZ + cc] = v1;
        }
    }
}

// ----------------------------------------------------------------- launch
extern "C" void kernel_launch(void* const* d_in, const int* in_sizes, int n_in,
                              void* d_out, int out_size) {
    const float* x  = (const float*)d_in[0];   // (16384, 512)
    const float* bw = (const float*)d_in[1];   // (512, 512)
    const float* cw = (const float*)d_in[2];   // (512, 512, 10)
    float* out = (float*)d_out;

    cudaFuncSetAttribute(gemm_hmma_kernel,
                         cudaFuncAttributeMaxDynamicSharedMemorySize, SMEM_BYTES);

    build_all_kernel<<<BSZ + (OUTSZ * KTOT) / 512, 512>>>(x, bw, cw);

    dim3 grid(OUTSZ / BN, BSZ / BM);   // (4, 128)
    gemm_hmma_kernel<<<grid, 128, SMEM_BYTES>>>(out);
}